// round 10
// baseline (speedup 1.0000x reference)
#include <cuda_runtime.h>
#include <cuda_bf16.h>
#include <mma.h>

using namespace nvcuda;

// Problem dims
#define BB 64
#define TT 512
#define DD 1024
#define HH 1024
#define G3 3072   // 3*H gates

// ---------------- device scratch (static, allowed) ----------------
// W order: 0=Wx0, 1=Wh0, 2=Wx1, 3=Wh1  (each [3072,1024], row-major)
__device__ __nv_bfloat16 g_Whi[4][G3 * HH];
__device__ __nv_bfloat16 g_Wlo[4][G3 * HH];
__device__ __nv_bfloat16 g_xhi[BB * TT * DD];
__device__ __nv_bfloat16 g_xlo[BB * TT * DD];
__device__ float g_GX0[TT * BB * G3];          // precomputed x-projection, layer 0 (no bias)
__device__ float g_gx1[2][BB * G3];            // layer1 x-side scratch (no bias)
__device__ __nv_bfloat16 g_h0hi[2][BB * HH];
__device__ __nv_bfloat16 g_h0lo[2][BB * HH];
__device__ __nv_bfloat16 g_h1hi[2][BB * HH];
__device__ __nv_bfloat16 g_h1lo[2][BB * HH];

// ---------------- init: fp32 -> bf16 hi/lo split ----------------
__global__ void split_kernel(int which, const float* __restrict__ src, int n) {
    __nv_bfloat16 *hi, *lo;
    switch (which) {
        case 0: hi = g_Whi[0]; lo = g_Wlo[0]; break;
        case 1: hi = g_Whi[1]; lo = g_Wlo[1]; break;
        case 2: hi = g_Whi[2]; lo = g_Wlo[2]; break;
        case 3: hi = g_Whi[3]; lo = g_Wlo[3]; break;
        default: hi = g_xhi;   lo = g_xlo;    break;
    }
    int i = blockIdx.x * blockDim.x + threadIdx.x;
    int stride = gridDim.x * blockDim.x;
    for (; i < n; i += stride) {
        float v = src[i];
        __nv_bfloat16 h = __float2bfloat16(v);
        hi[i] = h;
        lo[i] = __float2bfloat16(v - __bfloat162float(h));
    }
}

__global__ void zero_h_kernel() {
    int i = blockIdx.x * blockDim.x + threadIdx.x;
    const int N = 2 * BB * HH;
    __nv_bfloat16 z = __float2bfloat16(0.0f);
    if (i < N) {
        ((__nv_bfloat16*)g_h0hi)[i] = z;
        ((__nv_bfloat16*)g_h0lo)[i] = z;
        ((__nv_bfloat16*)g_h1hi)[i] = z;
        ((__nv_bfloat16*)g_h1lo)[i] = z;
    }
}

// ---------------- Phase A: GX0[(t,b), n] = x @ Wx0^T (no bias) ----------------
// Grid: (3072/128 = 24, 32768/128 = 256), 256 threads (8 warps).
// CTA tile: [128 m x 128 n]; warp w owns n-frag w (16 cols), loops 8 m-frags.
__global__ void __launch_bounds__(256) phaseA_kernel() {
    __shared__ __align__(32) __nv_bfloat16 As_hi[128][40];
    __shared__ __align__(32) __nv_bfloat16 As_lo[128][40];

    const int tid = threadIdx.x;
    const int wid = tid >> 5;
    const int n_w = blockIdx.x * 128 + wid * 16;   // global output column base for this warp
    const int m0  = blockIdx.y * 128;               // global (t,b) row base; r_global = m0+r; t=r>>6, b=r&63

    wmma::fragment<wmma::accumulator, 16, 16, 16, float> acc[8];
#pragma unroll
    for (int i = 0; i < 8; i++) wmma::fill_fragment(acc[i], 0.0f);

    const __nv_bfloat162* xh2 = (const __nv_bfloat162*)g_xhi;
    const __nv_bfloat162* xl2 = (const __nv_bfloat162*)g_xlo;

    for (int kc = 0; kc < 1024; kc += 32) {
        __syncthreads();
        // cooperative stage of A chunk [128 rows x 32 cols] hi+lo
        for (int l = tid; l < 128 * 16; l += 256) {
            int r  = l >> 4;
            int c2 = l & 15;
            int rg = m0 + r;
            int t = rg >> 6;
            int b = rg & 63;
            int off = ((b * TT + t) * DD + kc) / 2 + c2;
            ((__nv_bfloat162*)&As_hi[r][0])[c2] = xh2[off];
            ((__nv_bfloat162*)&As_lo[r][0])[c2] = xl2[off];
        }
        __syncthreads();
#pragma unroll
        for (int kk = 0; kk < 32; kk += 16) {
            wmma::fragment<wmma::matrix_b, 16, 16, 16, __nv_bfloat16, wmma::col_major> bhi, blo;
            wmma::load_matrix_sync(bhi, g_Whi[0] + (size_t)n_w * 1024 + kc + kk, 1024);
            wmma::load_matrix_sync(blo, g_Wlo[0] + (size_t)n_w * 1024 + kc + kk, 1024);
#pragma unroll
            for (int i = 0; i < 8; i++) {
                wmma::fragment<wmma::matrix_a, 16, 16, 16, __nv_bfloat16, wmma::row_major> ahi, alo;
                wmma::load_matrix_sync(ahi, &As_hi[16 * i][kk], 40);
                wmma::load_matrix_sync(alo, &As_lo[16 * i][kk], 40);
                wmma::mma_sync(acc[i], ahi, bhi, acc[i]);
                wmma::mma_sync(acc[i], ahi, blo, acc[i]);
                wmma::mma_sync(acc[i], alo, bhi, acc[i]);
            }
        }
    }
    // epilogue: frag i covers rows m0+16i .. m0+16i+15 -> single t, 16 b's
#pragma unroll
    for (int i = 0; i < 8; i++) {
        int rg = m0 + 16 * i;
        int t  = rg >> 6;
        int b0 = rg & 63;
        float* dst = g_GX0 + (size_t)(t * BB + b0) * G3 + n_w;
        wmma::store_matrix_sync(dst, acc[i], G3, wmma::mem_row_major);
    }
}

// ---------------- Phase kernel: one pipeline phase ----------------
// Grid: 192 blocks x 128 threads.
//  part 0 (blocks   0..63): layer0 step t=p   : gh0 = h0(t-1)@Wh0^T, combine -> h0(t)
//  part 1 (blocks  64..127): layer1 x  t=p-1 : gx1 = h0(t)@Wx1^T -> scratch
//  part 2 (blocks 128..191): layer1 h  t=p-2 : gh1 = h1(t-1)@Wh1^T, combine -> h1(t)
// Each block owns hidden slice j in [j0, j0+16), computing all 3 gates.
__global__ void __launch_bounds__(128) phase_kernel(
    int p,
    const float* __restrict__ bx0, const float* __restrict__ bh0,
    const float* __restrict__ bx1, const float* __restrict__ bh1)
{
    const int part = blockIdx.x >> 6;
    const int j0   = (blockIdx.x & 63) * 16;
    const int tid  = threadIdx.x;
    const int wid  = tid >> 5;

    int t;
    if (part == 0)      { t = p;     if (t > 511) return; }
    else if (part == 1) { t = p - 1; if (t < 0 || t > 511) return; }
    else                { t = p - 2; if (t < 0 || t > 511) return; }

    const __nv_bfloat16 *Ahi, *Alo, *Whi, *Wlo;
    if (part == 0) {        // A = h0(t-1)
        Ahi = g_h0hi[(t + 1) & 1]; Alo = g_h0lo[(t + 1) & 1];
        Whi = g_Whi[1];            Wlo = g_Wlo[1];
    } else if (part == 1) { // A = h0(t)
        Ahi = g_h0hi[t & 1];       Alo = g_h0lo[t & 1];
        Whi = g_Whi[2];            Wlo = g_Wlo[2];
    } else {                // A = h1(t-1)
        Ahi = g_h1hi[(t + 1) & 1]; Alo = g_h1lo[(t + 1) & 1];
        Whi = g_Whi[3];            Wlo = g_Wlo[3];
    }

    __shared__ __align__(32) __nv_bfloat16 Bs_hi[48][64];
    __shared__ __align__(32) __nv_bfloat16 Bs_lo[48][64];
    __shared__ __align__(32) float sacc[3][64][16];

    wmma::fragment<wmma::accumulator, 16, 16, 16, float> acc[3];
#pragma unroll
    for (int g = 0; g < 3; g++) wmma::fill_fragment(acc[g], 0.0f);

    const __nv_bfloat162* wh2 = (const __nv_bfloat162*)Whi;
    const __nv_bfloat162* wl2 = (const __nv_bfloat162*)Wlo;

    for (int kc = 0; kc < 1024; kc += 64) {
        __syncthreads();
        // stage B: 48 rows (3 gates x 16 j) x 64 k, hi+lo
        for (int l = tid; l < 48 * 32; l += 128) {
            int r  = l >> 5;     // 0..47
            int c2 = l & 31;     // bf162 col
            int row = (r >> 4) * 1024 + j0 + (r & 15);   // global W row
            int off = (row * 1024 + kc) / 2 + c2;
            ((__nv_bfloat162*)&Bs_hi[r][0])[c2] = wh2[off];
            ((__nv_bfloat162*)&Bs_lo[r][0])[c2] = wl2[off];
        }
        __syncthreads();
#pragma unroll
        for (int kk = 0; kk < 64; kk += 16) {
            wmma::fragment<wmma::matrix_a, 16, 16, 16, __nv_bfloat16, wmma::row_major> ahi, alo;
            wmma::load_matrix_sync(ahi, Ahi + wid * 16 * 1024 + kc + kk, 1024);
            wmma::load_matrix_sync(alo, Alo + wid * 16 * 1024 + kc + kk, 1024);
#pragma unroll
            for (int g = 0; g < 3; g++) {
                wmma::fragment<wmma::matrix_b, 16, 16, 16, __nv_bfloat16, wmma::col_major> bhi, blo;
                wmma::load_matrix_sync(bhi, &Bs_hi[g * 16][kk], 64);
                wmma::load_matrix_sync(blo, &Bs_lo[g * 16][kk], 64);
                wmma::mma_sync(acc[g], ahi, bhi, acc[g]);
                wmma::mma_sync(acc[g], ahi, blo, acc[g]);
                wmma::mma_sync(acc[g], alo, bhi, acc[g]);
            }
        }
    }
    __syncthreads();
#pragma unroll
    for (int g = 0; g < 3; g++)
        wmma::store_matrix_sync(&sacc[g][wid * 16][0], acc[g], 16, wmma::mem_row_major);
    __syncthreads();

    if (part == 1) {
        float* dst = g_gx1[t & 1];
        for (int l = tid; l < 64 * 16; l += 128) {
            int b = l >> 4, jj = l & 15;
            int j = j0 + jj;
            dst[b * G3 + j]        = sacc[0][b][jj];
            dst[b * G3 + 1024 + j] = sacc[1][b][jj];
            dst[b * G3 + 2048 + j] = sacc[2][b][jj];
        }
        return;
    }

    // GRU combine (part 0 or 2)
    const float* bx = (part == 0) ? bx0 : bx1;
    const float* bh = (part == 0) ? bh0 : bh1;
    __nv_bfloat16* outhi = (part == 0) ? g_h0hi[t & 1] : g_h1hi[t & 1];
    __nv_bfloat16* outlo = (part == 0) ? g_h0lo[t & 1] : g_h1lo[t & 1];

    for (int l = tid; l < 64 * 16; l += 128) {
        int b = l >> 4, jj = l & 15;
        int j = j0 + jj;
        float ir, iz, in_;
        if (part == 0) {
            const float* gxr = g_GX0 + (size_t)(t * BB + b) * G3;
            ir  = gxr[j]        + bx[j];
            iz  = gxr[1024 + j] + bx[1024 + j];
            in_ = gxr[2048 + j] + bx[2048 + j];
        } else {
            const float* gxr = g_gx1[t & 1] + b * G3;
            ir  = gxr[j]        + bx[j];
            iz  = gxr[1024 + j] + bx[1024 + j];
            in_ = gxr[2048 + j] + bx[2048 + j];
        }
        float hr = sacc[0][b][jj] + bh[j];
        float hz = sacc[1][b][jj] + bh[1024 + j];
        float hn = sacc[2][b][jj] + bh[2048 + j];

        float r = 1.0f / (1.0f + expf(-(ir + hr)));
        float z = 1.0f / (1.0f + expf(-(iz + hz)));
        float n = tanhf(in_ + r * hn);
        float hp = __bfloat162float(Ahi[b * HH + j]) + __bfloat162float(Alo[b * HH + j]);
        float hnew = n + z * (hp - n);

        __nv_bfloat16 hh = __float2bfloat16(hnew);
        outhi[b * HH + j] = hh;
        outlo[b * HH + j] = __float2bfloat16(hnew - __bfloat162float(hh));
    }
}

// ---------------- FC: out[b] = h1(511)[b,:] . fcW + fcb ----------------
__global__ void fc_kernel(const float* __restrict__ fcW, const float* __restrict__ fcb,
                          float* __restrict__ out) {
    const int b = blockIdx.x;
    const int tid = threadIdx.x;
    const __nv_bfloat16* hh = g_h1hi[1] + b * HH;   // t=511 -> buffer 1
    const __nv_bfloat16* hl = g_h1lo[1] + b * HH;
    float s = 0.0f;
    for (int k = tid; k < HH; k += 128)
        s += (__bfloat162float(hh[k]) + __bfloat162float(hl[k])) * fcW[k];
    __shared__ float red[128];
    red[tid] = s;
    __syncthreads();
    for (int o = 64; o > 0; o >>= 1) {
        if (tid < o) red[tid] += red[tid + o];
        __syncthreads();
    }
    if (tid == 0) out[b] = red[0] + fcb[0];
}

// ---------------- host ----------------
extern "C" void kernel_launch(void* const* d_in, const int* in_sizes, int n_in,
                              void* d_out, int out_size) {
    const float* x   = (const float*)d_in[0];
    const float* Wx0 = (const float*)d_in[1];
    const float* bx0 = (const float*)d_in[2];
    const float* Wh0 = (const float*)d_in[3];
    const float* bh0 = (const float*)d_in[4];
    const float* Wx1 = (const float*)d_in[5];
    const float* bx1 = (const float*)d_in[6];
    const float* Wh1 = (const float*)d_in[7];
    const float* bh1 = (const float*)d_in[8];
    const float* fcW = (const float*)d_in[9];
    const float* fcb = (const float*)d_in[10];
    float* out = (float*)d_out;

    const int nW = G3 * HH;       // 3,145,728
    const int nX = BB * TT * DD;  // 33,554,432

    // 1) split weights + x into bf16 hi/lo
    split_kernel<<<1024, 256>>>(0, Wx0, nW);
    split_kernel<<<1024, 256>>>(1, Wh0, nW);
    split_kernel<<<1024, 256>>>(2, Wx1, nW);
    split_kernel<<<1024, 256>>>(3, Wh1, nW);
    split_kernel<<<4096, 256>>>(4, x, nX);

    // 2) zero initial hidden states (both ping-pong slots)
    zero_h_kernel<<<(2 * BB * HH + 255) / 256, 256>>>();

    // 3) parallel x-projection for layer 0
    {
        dim3 grid(G3 / 128, (TT * BB) / 128);   // (24, 256)
        phaseA_kernel<<<grid, 256>>>();
    }

    // 4) pipelined recurrence: 514 phases
    for (int p = 0; p < 514; ++p)
        phase_kernel<<<192, 128>>>(p, bx0, bh0, bx1, bh1);

    // 5) final FC
    fc_kernel<<<BB, 128>>>(fcW, fcb, out);

    (void)in_sizes; (void)n_in; (void)out_size;
}

// round 12
// speedup vs baseline: 1.6108x; 1.6108x over previous
#include <cuda_runtime.h>
#include <cuda_bf16.h>
#include <mma.h>

using namespace nvcuda;

// Problem dims
#define BB 64
#define TT 512
#define DD 1024
#define HH 1024
#define G3 3072   // 3*H gates
#define NBLK 96   // persistent blocks (3 parts x 32 j-slices of width 32)

// ---------------- device scratch (static, allowed) ----------------
// W order: 0=Wx0, 1=Wh0, 2=Wx1, 3=Wh1  (each [3072,1024], row-major)
__device__ __nv_bfloat16 g_Whi[4][G3 * HH];
__device__ __nv_bfloat16 g_Wlo[4][G3 * HH];
__device__ __nv_bfloat16 g_xhi[BB * TT * DD];
__device__ __nv_bfloat16 g_xlo[BB * TT * DD];
__device__ float g_GX0[TT * BB * G3];          // precomputed x-projection, layer 0 (no bias)
__device__ float g_gx1[2][BB * G3];            // layer1 x-side scratch (no bias)
__device__ __nv_bfloat16 g_h0hi[2][BB * HH];
__device__ __nv_bfloat16 g_h0lo[2][BB * HH];
__device__ __nv_bfloat16 g_h1hi[2][BB * HH];
__device__ __nv_bfloat16 g_h1lo[2][BB * HH];

// grid barrier state (reset by init kernel every launch)
__device__ unsigned g_arrive;
__device__ unsigned g_release;

// ---------------- init: fp32 -> bf16 hi/lo split ----------------
__global__ void split_kernel(int which, const float* __restrict__ src, int n) {
    __nv_bfloat16 *hi, *lo;
    switch (which) {
        case 0: hi = g_Whi[0]; lo = g_Wlo[0]; break;
        case 1: hi = g_Whi[1]; lo = g_Wlo[1]; break;
        case 2: hi = g_Whi[2]; lo = g_Wlo[2]; break;
        case 3: hi = g_Whi[3]; lo = g_Wlo[3]; break;
        default: hi = g_xhi;   lo = g_xlo;    break;
    }
    int i = blockIdx.x * blockDim.x + threadIdx.x;
    int stride = gridDim.x * blockDim.x;
    for (; i < n; i += stride) {
        float v = src[i];
        __nv_bfloat16 h = __float2bfloat16(v);
        hi[i] = h;
        lo[i] = __float2bfloat16(v - __bfloat162float(h));
    }
}

__global__ void init_state_kernel() {
    int i = blockIdx.x * blockDim.x + threadIdx.x;
    if (i == 0) { g_arrive = 0; g_release = 0; }
    const int N = 2 * BB * HH;
    __nv_bfloat16 z = __float2bfloat16(0.0f);
    if (i < N) {
        ((__nv_bfloat16*)g_h0hi)[i] = z;
        ((__nv_bfloat16*)g_h0lo)[i] = z;
        ((__nv_bfloat16*)g_h1hi)[i] = z;
        ((__nv_bfloat16*)g_h1lo)[i] = z;
    }
}

// ---------------- Phase A: GX0[(t,b), n] = x @ Wx0^T (no bias) ----------------
__global__ void __launch_bounds__(256) phaseA_kernel() {
    __shared__ __align__(32) __nv_bfloat16 As_hi[128][40];
    __shared__ __align__(32) __nv_bfloat16 As_lo[128][40];

    const int tid = threadIdx.x;
    const int wid = tid >> 5;
    const int n_w = blockIdx.x * 128 + wid * 16;
    const int m0  = blockIdx.y * 128;

    wmma::fragment<wmma::accumulator, 16, 16, 16, float> acc[8];
#pragma unroll
    for (int i = 0; i < 8; i++) wmma::fill_fragment(acc[i], 0.0f);

    const __nv_bfloat162* xh2 = (const __nv_bfloat162*)g_xhi;
    const __nv_bfloat162* xl2 = (const __nv_bfloat162*)g_xlo;

    for (int kc = 0; kc < 1024; kc += 32) {
        __syncthreads();
        for (int l = tid; l < 128 * 16; l += 256) {
            int r  = l >> 4;
            int c2 = l & 15;
            int rg = m0 + r;
            int t = rg >> 6;
            int b = rg & 63;
            int off = ((b * TT + t) * DD + kc) / 2 + c2;
            ((__nv_bfloat162*)&As_hi[r][0])[c2] = xh2[off];
            ((__nv_bfloat162*)&As_lo[r][0])[c2] = xl2[off];
        }
        __syncthreads();
#pragma unroll
        for (int kk = 0; kk < 32; kk += 16) {
            wmma::fragment<wmma::matrix_b, 16, 16, 16, __nv_bfloat16, wmma::col_major> bhi, blo;
            wmma::load_matrix_sync(bhi, g_Whi[0] + (size_t)n_w * 1024 + kc + kk, 1024);
            wmma::load_matrix_sync(blo, g_Wlo[0] + (size_t)n_w * 1024 + kc + kk, 1024);
#pragma unroll
            for (int i = 0; i < 8; i++) {
                wmma::fragment<wmma::matrix_a, 16, 16, 16, __nv_bfloat16, wmma::row_major> ahi, alo;
                wmma::load_matrix_sync(ahi, &As_hi[16 * i][kk], 40);
                wmma::load_matrix_sync(alo, &As_lo[16 * i][kk], 40);
                wmma::mma_sync(acc[i], ahi, bhi, acc[i]);
                wmma::mma_sync(acc[i], ahi, blo, acc[i]);
                wmma::mma_sync(acc[i], alo, bhi, acc[i]);
            }
        }
    }
#pragma unroll
    for (int i = 0; i < 8; i++) {
        int rg = m0 + 16 * i;
        int t  = rg >> 6;
        int b0 = rg & 63;
        float* dst = g_GX0 + (size_t)(t * BB + b0) * G3 + n_w;
        wmma::store_matrix_sync(dst, acc[i], G3, wmma::mem_row_major);
    }
}

// ---------------- grid barrier ----------------
__device__ __forceinline__ void gsync(unsigned r) {
    __syncthreads();
    if (threadIdx.x == 0) {
        __threadfence();
        unsigned a = atomicAdd(&g_arrive, 1u);
        if (a == r * NBLK - 1u) {
            atomicExch(&g_release, r);
        } else {
            volatile unsigned* rel = &g_release;
            while (*rel < r) { }
        }
        __threadfence();
    }
    __syncthreads();
}

// ---------------- persistent recurrence kernel ----------------
// 96 blocks x 256 threads. block = (part, j0): part = bx/32, j0 = (bx%32)*32.
//  part 0: layer0 step t=p   : gh0 = h0(t-1)@Wh0^T, combine -> h0(t)
//  part 1: layer1 x  t=p-1   : gx1 = h0(t)@Wx1^T -> scratch
//  part 2: layer1 h  t=p-2   : gh1 = h1(t-1)@Wh1^T, combine -> h1(t)
// Each block computes all 3 gates for its 32-wide hidden slice (rows 96 of W).
// W_hi tile (96 x 1024 bf16) lives in SMEM for the whole kernel; W_lo streamed.
#define WHI_LD 1032              // 1024 + 8 pad (odd 16B stride -> 2-way LDSM max)
#define BLO_LD 72                // 64 + 8 pad
#define SACC_LD 36               // 32 + 4 pad (float)
#define SMEM_WHI_BYTES (96 * WHI_LD * 2)            // 198144
#define SMEM_UNION_BYTES (3 * 64 * SACC_LD * 4)     // 27648 (> 96*BLO_LD*2 = 13824)
#define SMEM_TOTAL_BYTES (SMEM_WHI_BYTES + SMEM_UNION_BYTES)  // 225792

__global__ void __launch_bounds__(256) recur_kernel(
    const float* __restrict__ bx0, const float* __restrict__ bh0,
    const float* __restrict__ bx1, const float* __restrict__ bh1)
{
    extern __shared__ __align__(16) unsigned char s_raw[];
    __nv_bfloat16* Whi_s = (__nv_bfloat16*)s_raw;
    __nv_bfloat16* Blo_s = (__nv_bfloat16*)(s_raw + SMEM_WHI_BYTES);
    float*         saccf = (float*)(s_raw + SMEM_WHI_BYTES);   // union with Blo_s

    const int tid  = threadIdx.x;
    const int wid  = tid >> 5;
    const int part = blockIdx.x >> 5;           // 0..2
    const int j0   = (blockIdx.x & 31) * 32;    // hidden slice base
    const int ms   = wid >> 1;                  // A row slice (0..3) -> rows [16*ms,+16)
    const int nf   = wid & 1;                   // n sub-frag (0..1) -> j offset 16*nf

    const int widx = part + 1;                  // W matrix: 1=Wh0, 2=Wx1, 3=Wh1

    // ---- load this block's W_hi tile into SMEM (once per launch) ----
    {
        const uint4* src = (const uint4*)(g_Whi[widx]);
        for (int l = tid; l < 96 * 128; l += 256) {
            int r = l >> 7, c = l & 127;
            int grow = (r >> 5) * 1024 + j0 + (r & 31);
            *(uint4*)&Whi_s[r * WHI_LD + c * 8] = src[grow * 128 + c];
        }
    }
    __syncthreads();

    const uint4* wlo_src = (const uint4*)(g_Wlo[widx]);
    const float* bx = (part == 0) ? bx0 : bx1;
    const float* bh = (part == 0) ? bh0 : bh1;

    for (int p = 0; p < 514; ++p) {
        int t;
        bool valid;
        if (part == 0)      { t = p;     valid = (t <= 511); }
        else if (part == 1) { t = p - 1; valid = (t >= 0 && t <= 511); }
        else                { t = p - 2; valid = (t >= 0 && t <= 511); }

        if (valid) {
            const __nv_bfloat16 *Ahi, *Alo;
            if (part == 0)      { Ahi = g_h0hi[(t + 1) & 1]; Alo = g_h0lo[(t + 1) & 1]; }
            else if (part == 1) { Ahi = g_h0hi[t & 1];       Alo = g_h0lo[t & 1]; }
            else                { Ahi = g_h1hi[(t + 1) & 1]; Alo = g_h1lo[(t + 1) & 1]; }

            wmma::fragment<wmma::accumulator, 16, 16, 16, float> acc[3];
#pragma unroll
            for (int g = 0; g < 3; g++) wmma::fill_fragment(acc[g], 0.0f);

            const __nv_bfloat16* a_hi_base = Ahi + ms * 16 * 1024;
            const __nv_bfloat16* a_lo_base = Alo + ms * 16 * 1024;

            for (int kc = 0; kc < 1024; kc += 64) {
                __syncthreads();  // protect union buffer (prev combine / prev chunk)
                // stage W_lo chunk: 96 rows x 64 k
                for (int l = tid; l < 96 * 8; l += 256) {
                    int r = l >> 3, c = l & 7;
                    int grow = (r >> 5) * 1024 + j0 + (r & 31);
                    *(uint4*)&Blo_s[r * BLO_LD + c * 8] = wlo_src[grow * 128 + (kc >> 3) + c];
                }
                __syncthreads();
#pragma unroll
                for (int kk = 0; kk < 64; kk += 16) {
                    wmma::fragment<wmma::matrix_a, 16, 16, 16, __nv_bfloat16, wmma::row_major> ahi, alo;
                    wmma::load_matrix_sync(ahi, a_hi_base + kc + kk, 1024);
                    wmma::load_matrix_sync(alo, a_lo_base + kc + kk, 1024);
#pragma unroll
                    for (int g = 0; g < 3; g++) {
                        wmma::fragment<wmma::matrix_b, 16, 16, 16, __nv_bfloat16, wmma::col_major> bhi, blo;
                        wmma::load_matrix_sync(bhi, &Whi_s[(g * 32 + nf * 16) * WHI_LD + kc + kk], WHI_LD);
                        wmma::load_matrix_sync(blo, &Blo_s[(g * 32 + nf * 16) * BLO_LD + kk], BLO_LD);
                        wmma::mma_sync(acc[g], ahi, bhi, acc[g]);
                        wmma::mma_sync(acc[g], ahi, blo, acc[g]);
                        wmma::mma_sync(acc[g], alo, bhi, acc[g]);
                    }
                }
            }
            __syncthreads();   // mma done reading Blo_s -> safe to write sacc (union)
#pragma unroll
            for (int g = 0; g < 3; g++)
                wmma::store_matrix_sync(saccf + (g * 64 + ms * 16) * SACC_LD + nf * 16,
                                        acc[g], SACC_LD, wmma::mem_row_major);
            __syncthreads();

            if (part == 1) {
                float* dst = g_gx1[t & 1];
                for (int l = tid; l < 64 * 32; l += 256) {
                    int b = l >> 5, jj = l & 31;
                    int j = j0 + jj;
                    dst[b * G3 + j]        = saccf[(0 * 64 + b) * SACC_LD + jj];
                    dst[b * G3 + 1024 + j] = saccf[(1 * 64 + b) * SACC_LD + jj];
                    dst[b * G3 + 2048 + j] = saccf[(2 * 64 + b) * SACC_LD + jj];
                }
            } else {
                __nv_bfloat16* outhi = (part == 0) ? g_h0hi[t & 1] : g_h1hi[t & 1];
                __nv_bfloat16* outlo = (part == 0) ? g_h0lo[t & 1] : g_h1lo[t & 1];
                for (int l = tid; l < 64 * 32; l += 256) {
                    int b = l >> 5, jj = l & 31;
                    int j = j0 + jj;
                    float ir, iz, in_;
                    if (part == 0) {
                        const float* gxr = g_GX0 + (size_t)(t * BB + b) * G3;
                        ir  = gxr[j]        + bx[j];
                        iz  = gxr[1024 + j] + bx[1024 + j];
                        in_ = gxr[2048 + j] + bx[2048 + j];
                    } else {
                        const float* gxr = g_gx1[t & 1] + b * G3;
                        ir  = gxr[j]        + bx[j];
                        iz  = gxr[1024 + j] + bx[1024 + j];
                        in_ = gxr[2048 + j] + bx[2048 + j];
                    }
                    float hr = saccf[(0 * 64 + b) * SACC_LD + jj] + bh[j];
                    float hz = saccf[(1 * 64 + b) * SACC_LD + jj] + bh[1024 + j];
                    float hn = saccf[(2 * 64 + b) * SACC_LD + jj] + bh[2048 + j];

                    float r = 1.0f / (1.0f + expf(-(ir + hr)));
                    float z = 1.0f / (1.0f + expf(-(iz + hz)));
                    float n = tanhf(in_ + r * hn);
                    float hp = __bfloat162float(Ahi[b * HH + j]) + __bfloat162float(Alo[b * HH + j]);
                    float hnew = n + z * (hp - n);

                    __nv_bfloat16 hh = __float2bfloat16(hnew);
                    outhi[b * HH + j] = hh;
                    outlo[b * HH + j] = __float2bfloat16(hnew - __bfloat162float(hh));
                }
            }
        }

        gsync((unsigned)(p + 1));
    }
}

// ---------------- FC: out[b] = h1(511)[b,:] . fcW + fcb ----------------
__global__ void fc_kernel(const float* __restrict__ fcW, const float* __restrict__ fcb,
                          float* __restrict__ out) {
    const int b = blockIdx.x;
    const int tid = threadIdx.x;
    const __nv_bfloat16* hh = g_h1hi[1] + b * HH;   // t=511 -> buffer 1
    const __nv_bfloat16* hl = g_h1lo[1] + b * HH;
    float s = 0.0f;
    for (int k = tid; k < HH; k += 128)
        s += (__bfloat162float(hh[k]) + __bfloat162float(hl[k])) * fcW[k];
    __shared__ float red[128];
    red[tid] = s;
    __syncthreads();
    for (int o = 64; o > 0; o >>= 1) {
        if (tid < o) red[tid] += red[tid + o];
        __syncthreads();
    }
    if (tid == 0) out[b] = red[0] + fcb[0];
}

// ---------------- host ----------------
extern "C" void kernel_launch(void* const* d_in, const int* in_sizes, int n_in,
                              void* d_out, int out_size) {
    const float* x   = (const float*)d_in[0];
    const float* Wx0 = (const float*)d_in[1];
    const float* bx0 = (const float*)d_in[2];
    const float* Wh0 = (const float*)d_in[3];
    const float* bh0 = (const float*)d_in[4];
    const float* Wx1 = (const float*)d_in[5];
    const float* bx1 = (const float*)d_in[6];
    const float* Wh1 = (const float*)d_in[7];
    const float* bh1 = (const float*)d_in[8];
    const float* fcW = (const float*)d_in[9];
    const float* fcb = (const float*)d_in[10];
    float* out = (float*)d_out;

    const int nW = G3 * HH;
    const int nX = BB * TT * DD;

    static int smem_set = 0;
    if (!smem_set) {
        cudaFuncSetAttribute(recur_kernel, cudaFuncAttributeMaxDynamicSharedMemorySize,
                             SMEM_TOTAL_BYTES);
        smem_set = 1;
    }

    // 1) split weights + x into bf16 hi/lo
    split_kernel<<<1024, 256>>>(0, Wx0, nW);
    split_kernel<<<1024, 256>>>(1, Wh0, nW);
    split_kernel<<<1024, 256>>>(2, Wx1, nW);
    split_kernel<<<1024, 256>>>(3, Wh1, nW);
    split_kernel<<<4096, 256>>>(4, x, nX);

    // 2) zero initial hidden states + reset grid barrier
    init_state_kernel<<<(2 * BB * HH + 255) / 256, 256>>>();

    // 3) parallel x-projection for layer 0
    {
        dim3 grid(G3 / 128, (TT * BB) / 128);   // (24, 256)
        phaseA_kernel<<<grid, 256>>>();
    }

    // 4) persistent pipelined recurrence: 514 phases, one kernel
    recur_kernel<<<NBLK, 256, SMEM_TOTAL_BYTES>>>(bx0, bh0, bx1, bh1);

    // 5) final FC
    fc_kernel<<<BB, 128>>>(fcW, fcb, out);

    (void)in_sizes; (void)n_in; (void)out_size;
}

// round 13
// speedup vs baseline: 1.9025x; 1.1811x over previous
#include <cuda_runtime.h>
#include <cuda_bf16.h>
#include <mma.h>

using namespace nvcuda;

// Problem dims
#define BB 64
#define TT 512
#define DD 1024
#define HH 1024
#define G3 3072   // 3*H gates
#define NBLK 96   // persistent blocks (3 parts x 32 j-slices of width 32)

// ---------------- device scratch (static, allowed) ----------------
// W order: 0=Wx0, 1=Wh0, 2=Wx1, 3=Wh1  (each [3072,1024], row-major)
__device__ __nv_bfloat16 g_Whi[4][G3 * HH];
__device__ __nv_bfloat16 g_Wlo[4][G3 * HH];
__device__ __nv_bfloat16 g_xhi[BB * TT * DD];
__device__ __nv_bfloat16 g_xlo[BB * TT * DD];
__device__ float g_GX0[TT * BB * G3];          // precomputed x-projection, layer 0 (no bias)
__device__ float g_gx1[2][BB * G3];            // layer1 x-side scratch (no bias)
__device__ __nv_bfloat16 g_h0hi[2][BB * HH];
__device__ __nv_bfloat16 g_h0lo[2][BB * HH];
__device__ __nv_bfloat16 g_h1hi[2][BB * HH];
__device__ __nv_bfloat16 g_h1lo[2][BB * HH];

// grid barrier state (reset by init kernel every launch)
__device__ unsigned g_arrive;
__device__ unsigned g_release;

// ---------------- init: fp32 -> bf16 hi/lo split ----------------
__global__ void split_kernel(int which, const float* __restrict__ src, int n) {
    __nv_bfloat16 *hi, *lo;
    switch (which) {
        case 0: hi = g_Whi[0]; lo = g_Wlo[0]; break;
        case 1: hi = g_Whi[1]; lo = g_Wlo[1]; break;
        case 2: hi = g_Whi[2]; lo = g_Wlo[2]; break;
        case 3: hi = g_Whi[3]; lo = g_Wlo[3]; break;
        default: hi = g_xhi;   lo = g_xlo;    break;
    }
    int i = blockIdx.x * blockDim.x + threadIdx.x;
    int stride = gridDim.x * blockDim.x;
    for (; i < n; i += stride) {
        float v = src[i];
        __nv_bfloat16 h = __float2bfloat16(v);
        hi[i] = h;
        lo[i] = __float2bfloat16(v - __bfloat162float(h));
    }
}

__global__ void init_state_kernel() {
    int i = blockIdx.x * blockDim.x + threadIdx.x;
    if (i == 0) { g_arrive = 0; g_release = 0; }
    const int N = 2 * BB * HH;
    __nv_bfloat16 z = __float2bfloat16(0.0f);
    if (i < N) {
        ((__nv_bfloat16*)g_h0hi)[i] = z;
        ((__nv_bfloat16*)g_h0lo)[i] = z;
        ((__nv_bfloat16*)g_h1hi)[i] = z;
        ((__nv_bfloat16*)g_h1lo)[i] = z;
    }
}

// ---------------- Phase A: GX0[(t,b), n] = x @ Wx0^T (no bias) ----------------
__global__ void __launch_bounds__(256) phaseA_kernel() {
    __shared__ __align__(32) __nv_bfloat16 As_hi[128][40];
    __shared__ __align__(32) __nv_bfloat16 As_lo[128][40];

    const int tid = threadIdx.x;
    const int wid = tid >> 5;
    const int n_w = blockIdx.x * 128 + wid * 16;
    const int m0  = blockIdx.y * 128;

    wmma::fragment<wmma::accumulator, 16, 16, 16, float> acc[8];
#pragma unroll
    for (int i = 0; i < 8; i++) wmma::fill_fragment(acc[i], 0.0f);

    const __nv_bfloat162* xh2 = (const __nv_bfloat162*)g_xhi;
    const __nv_bfloat162* xl2 = (const __nv_bfloat162*)g_xlo;

    for (int kc = 0; kc < 1024; kc += 32) {
        __syncthreads();
        for (int l = tid; l < 128 * 16; l += 256) {
            int r  = l >> 4;
            int c2 = l & 15;
            int rg = m0 + r;
            int t = rg >> 6;
            int b = rg & 63;
            int off = ((b * TT + t) * DD + kc) / 2 + c2;
            ((__nv_bfloat162*)&As_hi[r][0])[c2] = xh2[off];
            ((__nv_bfloat162*)&As_lo[r][0])[c2] = xl2[off];
        }
        __syncthreads();
#pragma unroll
        for (int kk = 0; kk < 32; kk += 16) {
            wmma::fragment<wmma::matrix_b, 16, 16, 16, __nv_bfloat16, wmma::col_major> bhi, blo;
            wmma::load_matrix_sync(bhi, g_Whi[0] + (size_t)n_w * 1024 + kc + kk, 1024);
            wmma::load_matrix_sync(blo, g_Wlo[0] + (size_t)n_w * 1024 + kc + kk, 1024);
#pragma unroll
            for (int i = 0; i < 8; i++) {
                wmma::fragment<wmma::matrix_a, 16, 16, 16, __nv_bfloat16, wmma::row_major> ahi, alo;
                wmma::load_matrix_sync(ahi, &As_hi[16 * i][kk], 40);
                wmma::load_matrix_sync(alo, &As_lo[16 * i][kk], 40);
                wmma::mma_sync(acc[i], ahi, bhi, acc[i]);
                wmma::mma_sync(acc[i], ahi, blo, acc[i]);
                wmma::mma_sync(acc[i], alo, bhi, acc[i]);
            }
        }
    }
#pragma unroll
    for (int i = 0; i < 8; i++) {
        int rg = m0 + 16 * i;
        int t  = rg >> 6;
        int b0 = rg & 63;
        float* dst = g_GX0 + (size_t)(t * BB + b0) * G3 + n_w;
        wmma::store_matrix_sync(dst, acc[i], G3, wmma::mem_row_major);
    }
}

// ---------------- grid barrier ----------------
__device__ __forceinline__ void gsync(unsigned r) {
    __syncthreads();
    if (threadIdx.x == 0) {
        __threadfence();
        unsigned a = atomicAdd(&g_arrive, 1u);
        if (a == r * NBLK - 1u) {
            atomicExch(&g_release, r);
        } else {
            volatile unsigned* rel = &g_release;
            while (*rel < r) { }
        }
        __threadfence();
    }
    __syncthreads();
}

// ---------------- persistent recurrence kernel ----------------
// 96 blocks x 256 threads. block = (part, j0): part = bx/32, j0 = (bx%32)*32.
//  part 0: layer0 step t=p   : gh0 = h0(t-1)@Wh0^T, combine -> h0(t)
//  part 1: layer1 x  t=p-1   : gx1 = h0(t)@Wx1^T -> scratch
//  part 2: layer1 h  t=p-2   : gh1 = h1(t-1)@Wh1^T, combine -> h1(t)
// Each block computes all 3 gates for its 32-wide hidden slice (rows 96 of W).
// W_hi tile (96 x 1024 bf16) lives in SMEM for the whole kernel; W_lo + A staged per chunk.
#define WHI_LD 1032              // 1024 + 8 pad (odd 16B stride -> limited LDSM conflicts)
#define AS_LD 72                 // 64 + 8 pad
#define BLO_LD 72                // 64 + 8 pad
#define SACC_LD 36               // 32 + 4 pad (float)
#define SMEM_WHI_BYTES (96 * WHI_LD * 2)            // 198144
// union region: A stage (2 * 64 * AS_LD * 2 = 18432) + Wlo stage (96 * BLO_LD * 2 = 13824) = 32256
//               vs sacc (3 * 64 * SACC_LD * 4 = 27648)  -> 32256
#define SMEM_UNION_BYTES 32256
#define SMEM_TOTAL_BYTES (SMEM_WHI_BYTES + SMEM_UNION_BYTES)  // 230400

__global__ void __launch_bounds__(256) recur_kernel(
    const float* __restrict__ bx0, const float* __restrict__ bh0,
    const float* __restrict__ bx1, const float* __restrict__ bh1)
{
    extern __shared__ __align__(16) unsigned char s_raw[];
    __nv_bfloat16* Whi_s = (__nv_bfloat16*)s_raw;
    __nv_bfloat16* As_hi = (__nv_bfloat16*)(s_raw + SMEM_WHI_BYTES);
    __nv_bfloat16* As_lo = As_hi + 64 * AS_LD;
    __nv_bfloat16* Blo_s = As_lo + 64 * AS_LD;
    float*         saccf = (float*)(s_raw + SMEM_WHI_BYTES);   // union with staging

    const int tid  = threadIdx.x;
    const int wid  = tid >> 5;
    const int part = blockIdx.x >> 5;           // 0..2
    const int j0   = (blockIdx.x & 31) * 32;    // hidden slice base
    const int ms   = wid >> 1;                  // A row slice (0..3) -> rows [16*ms,+16)
    const int nf   = wid & 1;                   // n sub-frag (0..1) -> j offset 16*nf

    const int widx = part + 1;                  // W matrix: 1=Wh0, 2=Wx1, 3=Wh1

    // ---- load this block's W_hi tile into SMEM (once per launch) ----
    {
        const uint4* src = (const uint4*)(g_Whi[widx]);
        for (int l = tid; l < 96 * 128; l += 256) {
            int r = l >> 7, c = l & 127;
            int grow = (r >> 5) * 1024 + j0 + (r & 31);
            *(uint4*)&Whi_s[r * WHI_LD + c * 8] = src[grow * 128 + c];
        }
    }
    __syncthreads();

    const uint4* wlo_src = (const uint4*)(g_Wlo[widx]);
    const float* bx = (part == 0) ? bx0 : bx1;
    const float* bh = (part == 0) ? bh0 : bh1;

    for (int p = 0; p < 514; ++p) {
        int t;
        bool valid;
        if (part == 0)      { t = p;     valid = (t <= 511); }
        else if (part == 1) { t = p - 1; valid = (t >= 0 && t <= 511); }
        else                { t = p - 2; valid = (t >= 0 && t <= 511); }

        if (valid) {
            const __nv_bfloat16 *Ahi, *Alo;
            if (part == 0)      { Ahi = g_h0hi[(t + 1) & 1]; Alo = g_h0lo[(t + 1) & 1]; }
            else if (part == 1) { Ahi = g_h0hi[t & 1];       Alo = g_h0lo[t & 1]; }
            else                { Ahi = g_h1hi[(t + 1) & 1]; Alo = g_h1lo[(t + 1) & 1]; }

            const uint4* a_hi4 = (const uint4*)Ahi;
            const uint4* a_lo4 = (const uint4*)Alo;

            wmma::fragment<wmma::accumulator, 16, 16, 16, float> acc[3];
#pragma unroll
            for (int g = 0; g < 3; g++) wmma::fill_fragment(acc[g], 0.0f);

            for (int kc = 0; kc < 1024; kc += 64) {
                __syncthreads();  // protect union buffer (prev combine / prev chunk frag reads)
                // stage A chunk: 64 rows x 64 k, hi+lo  (1024 uint4 -> 4/thread)
                {
                    int kq = kc >> 3;
#pragma unroll
                    for (int l = tid; l < 1024; l += 256) {
                        int half = l >> 9;           // 0 = hi, 1 = lo
                        int r = (l >> 3) & 63;
                        int c = l & 7;
                        uint4 v = (half ? a_lo4 : a_hi4)[r * 128 + kq + c];
                        __nv_bfloat16* dst = half ? As_lo : As_hi;
                        *(uint4*)&dst[r * AS_LD + c * 8] = v;
                    }
                    // stage W_lo chunk: 96 rows x 64 k (768 uint4 -> 3/thread)
#pragma unroll
                    for (int l = tid; l < 768; l += 256) {
                        int r = l >> 3, c = l & 7;
                        int grow = (r >> 5) * 1024 + j0 + (r & 31);
                        *(uint4*)&Blo_s[r * BLO_LD + c * 8] = wlo_src[grow * 128 + kq + c];
                    }
                }
                __syncthreads();
#pragma unroll
                for (int kk = 0; kk < 64; kk += 16) {
                    wmma::fragment<wmma::matrix_a, 16, 16, 16, __nv_bfloat16, wmma::row_major> ahi, alo;
                    wmma::load_matrix_sync(ahi, &As_hi[ms * 16 * AS_LD + kk], AS_LD);
                    wmma::load_matrix_sync(alo, &As_lo[ms * 16 * AS_LD + kk], AS_LD);
#pragma unroll
                    for (int g = 0; g < 3; g++) {
                        wmma::fragment<wmma::matrix_b, 16, 16, 16, __nv_bfloat16, wmma::col_major> bhi, blo;
                        wmma::load_matrix_sync(bhi, &Whi_s[(g * 32 + nf * 16) * WHI_LD + kc + kk], WHI_LD);
                        wmma::load_matrix_sync(blo, &Blo_s[(g * 32 + nf * 16) * BLO_LD + kk], BLO_LD);
                        wmma::mma_sync(acc[g], ahi, bhi, acc[g]);
                        wmma::mma_sync(acc[g], ahi, blo, acc[g]);
                        wmma::mma_sync(acc[g], alo, bhi, acc[g]);
                    }
                }
            }
            __syncthreads();   // mma done reading staging -> safe to write sacc (union)
#pragma unroll
            for (int g = 0; g < 3; g++)
                wmma::store_matrix_sync(saccf + (g * 64 + ms * 16) * SACC_LD + nf * 16,
                                        acc[g], SACC_LD, wmma::mem_row_major);
            __syncthreads();

            if (part == 1) {
                float* dst = g_gx1[t & 1];
                for (int l = tid; l < 64 * 32; l += 256) {
                    int b = l >> 5, jj = l & 31;
                    int j = j0 + jj;
                    dst[b * G3 + j]        = saccf[(0 * 64 + b) * SACC_LD + jj];
                    dst[b * G3 + 1024 + j] = saccf[(1 * 64 + b) * SACC_LD + jj];
                    dst[b * G3 + 2048 + j] = saccf[(2 * 64 + b) * SACC_LD + jj];
                }
            } else {
                __nv_bfloat16* outhi = (part == 0) ? g_h0hi[t & 1] : g_h1hi[t & 1];
                __nv_bfloat16* outlo = (part == 0) ? g_h0lo[t & 1] : g_h1lo[t & 1];
                for (int l = tid; l < 64 * 32; l += 256) {
                    int b = l >> 5, jj = l & 31;
                    int j = j0 + jj;
                    float ir, iz, in_;
                    if (part == 0) {
                        const float* gxr = g_GX0 + (size_t)(t * BB + b) * G3;
                        ir  = gxr[j]        + bx[j];
                        iz  = gxr[1024 + j] + bx[1024 + j];
                        in_ = gxr[2048 + j] + bx[2048 + j];
                    } else {
                        const float* gxr = g_gx1[t & 1] + b * G3;
                        ir  = gxr[j]        + bx[j];
                        iz  = gxr[1024 + j] + bx[1024 + j];
                        in_ = gxr[2048 + j] + bx[2048 + j];
                    }
                    float hr = saccf[(0 * 64 + b) * SACC_LD + jj] + bh[j];
                    float hz = saccf[(1 * 64 + b) * SACC_LD + jj] + bh[1024 + j];
                    float hn = saccf[(2 * 64 + b) * SACC_LD + jj] + bh[2048 + j];

                    float r = 1.0f / (1.0f + expf(-(ir + hr)));
                    float z = 1.0f / (1.0f + expf(-(iz + hz)));
                    float n = tanhf(in_ + r * hn);
                    float hp = __bfloat162float(Ahi[b * HH + j]) + __bfloat162float(Alo[b * HH + j]);
                    float hnew = n + z * (hp - n);

                    __nv_bfloat16 hh = __float2bfloat16(hnew);
                    outhi[b * HH + j] = hh;
                    outlo[b * HH + j] = __float2bfloat16(hnew - __bfloat162float(hh));
                }
            }
        }

        gsync((unsigned)(p + 1));
    }
}

// ---------------- FC: out[b] = h1(511)[b,:] . fcW + fcb ----------------
__global__ void fc_kernel(const float* __restrict__ fcW, const float* __restrict__ fcb,
                          float* __restrict__ out) {
    const int b = blockIdx.x;
    const int tid = threadIdx.x;
    const __nv_bfloat16* hh = g_h1hi[1] + b * HH;   // t=511 -> buffer 1
    const __nv_bfloat16* hl = g_h1lo[1] + b * HH;
    float s = 0.0f;
    for (int k = tid; k < HH; k += 128)
        s += (__bfloat162float(hh[k]) + __bfloat162float(hl[k])) * fcW[k];
    __shared__ float red[128];
    red[tid] = s;
    __syncthreads();
    for (int o = 64; o > 0; o >>= 1) {
        if (tid < o) red[tid] += red[tid + o];
        __syncthreads();
    }
    if (tid == 0) out[b] = red[0] + fcb[0];
}

// ---------------- host ----------------
extern "C" void kernel_launch(void* const* d_in, const int* in_sizes, int n_in,
                              void* d_out, int out_size) {
    const float* x   = (const float*)d_in[0];
    const float* Wx0 = (const float*)d_in[1];
    const float* bx0 = (const float*)d_in[2];
    const float* Wh0 = (const float*)d_in[3];
    const float* bh0 = (const float*)d_in[4];
    const float* Wx1 = (const float*)d_in[5];
    const float* bx1 = (const float*)d_in[6];
    const float* Wh1 = (const float*)d_in[7];
    const float* bh1 = (const float*)d_in[8];
    const float* fcW = (const float*)d_in[9];
    const float* fcb = (const float*)d_in[10];
    float* out = (float*)d_out;

    const int nW = G3 * HH;
    const int nX = BB * TT * DD;

    static int smem_set = 0;
    if (!smem_set) {
        cudaFuncSetAttribute(recur_kernel, cudaFuncAttributeMaxDynamicSharedMemorySize,
                             SMEM_TOTAL_BYTES);
        smem_set = 1;
    }

    // 1) split weights + x into bf16 hi/lo
    split_kernel<<<1024, 256>>>(0, Wx0, nW);
    split_kernel<<<1024, 256>>>(1, Wh0, nW);
    split_kernel<<<1024, 256>>>(2, Wx1, nW);
    split_kernel<<<1024, 256>>>(3, Wh1, nW);
    split_kernel<<<4096, 256>>>(4, x, nX);

    // 2) zero initial hidden states + reset grid barrier
    init_state_kernel<<<(2 * BB * HH + 255) / 256, 256>>>();

    // 3) parallel x-projection for layer 0
    {
        dim3 grid(G3 / 128, (TT * BB) / 128);   // (24, 256)
        phaseA_kernel<<<grid, 256>>>();
    }

    // 4) persistent pipelined recurrence: 514 phases, one kernel
    recur_kernel<<<NBLK, 256, SMEM_TOTAL_BYTES>>>(bx0, bh0, bx1, bh1);

    // 5) final FC
    fc_kernel<<<BB, 128>>>(fcW, fcb, out);

    (void)in_sizes; (void)n_in; (void)out_size;
}

// round 15
// speedup vs baseline: 2.2962x; 1.2069x over previous
#include <cuda_runtime.h>
#include <cuda_bf16.h>
#include <mma.h>

using namespace nvcuda;

// Problem dims
#define BB 64
#define TT 512
#define DD 1024
#define HH 1024
#define G3 3072   // 3*H gates
#define NBLK 96   // persistent blocks (3 parts x 32 j-slices of width 32)

// ---------------- device scratch (static, allowed) ----------------
// W order: 0=Wx0, 1=Wh0, 2=Wx1, 3=Wh1  (each [3072,1024], row-major)
__device__ __nv_bfloat16 g_Whi[4][G3 * HH];
__device__ __nv_bfloat16 g_Wlo[4][G3 * HH];
__device__ __nv_bfloat16 g_xhi[BB * TT * DD];
__device__ __nv_bfloat16 g_xlo[BB * TT * DD];
__device__ float g_GX0[TT * BB * G3];          // precomputed x-projection, layer 0 (no bias)
__device__ float g_gx1[2][BB * G3];            // layer1 x-side scratch (no bias)
__device__ __nv_bfloat16 g_h0hi[2][BB * HH];
__device__ __nv_bfloat16 g_h0lo[2][BB * HH];
__device__ __nv_bfloat16 g_h1hi[2][BB * HH];
__device__ __nv_bfloat16 g_h1lo[2][BB * HH];

// grid barrier state (reset by init kernel every launch)
__device__ unsigned g_arrive;
__device__ unsigned g_release;

// ---------------- cp.async helpers ----------------
#define CP_ASYNC16(dst_u32, src_ptr) \
    asm volatile("cp.async.cg.shared.global [%0], [%1], 16;\n" :: "r"(dst_u32), "l"(src_ptr))
#define CP_COMMIT() asm volatile("cp.async.commit_group;\n" ::: "memory")
#define CP_WAIT0()  asm volatile("cp.async.wait_group 0;\n" ::: "memory")

// ---------------- init: fp32 -> bf16 hi/lo split ----------------
__global__ void split_kernel(int which, const float* __restrict__ src, int n) {
    __nv_bfloat16 *hi, *lo;
    switch (which) {
        case 0: hi = g_Whi[0]; lo = g_Wlo[0]; break;
        case 1: hi = g_Whi[1]; lo = g_Wlo[1]; break;
        case 2: hi = g_Whi[2]; lo = g_Wlo[2]; break;
        case 3: hi = g_Whi[3]; lo = g_Wlo[3]; break;
        default: hi = g_xhi;   lo = g_xlo;    break;
    }
    int i = blockIdx.x * blockDim.x + threadIdx.x;
    int stride = gridDim.x * blockDim.x;
    for (; i < n; i += stride) {
        float v = src[i];
        __nv_bfloat16 h = __float2bfloat16(v);
        hi[i] = h;
        lo[i] = __float2bfloat16(v - __bfloat162float(h));
    }
}

__global__ void init_state_kernel() {
    int i = blockIdx.x * blockDim.x + threadIdx.x;
    if (i == 0) { g_arrive = 0; g_release = 0; }
    const int N = 2 * BB * HH;
    __nv_bfloat16 z = __float2bfloat16(0.0f);
    if (i < N) {
        ((__nv_bfloat16*)g_h0hi)[i] = z;
        ((__nv_bfloat16*)g_h0lo)[i] = z;
        ((__nv_bfloat16*)g_h1hi)[i] = z;
        ((__nv_bfloat16*)g_h1lo)[i] = z;
    }
}

// ---------------- Phase A: GX0[(t,b), n] = x @ Wx0^T (no bias) ----------------
__global__ void __launch_bounds__(256) phaseA_kernel() {
    __shared__ __align__(32) __nv_bfloat16 As_hi[128][40];
    __shared__ __align__(32) __nv_bfloat16 As_lo[128][40];

    const int tid = threadIdx.x;
    const int wid = tid >> 5;
    const int n_w = blockIdx.x * 128 + wid * 16;
    const int m0  = blockIdx.y * 128;

    wmma::fragment<wmma::accumulator, 16, 16, 16, float> acc[8];
#pragma unroll
    for (int i = 0; i < 8; i++) wmma::fill_fragment(acc[i], 0.0f);

    const __nv_bfloat162* xh2 = (const __nv_bfloat162*)g_xhi;
    const __nv_bfloat162* xl2 = (const __nv_bfloat162*)g_xlo;

    for (int kc = 0; kc < 1024; kc += 32) {
        __syncthreads();
        for (int l = tid; l < 128 * 16; l += 256) {
            int r  = l >> 4;
            int c2 = l & 15;
            int rg = m0 + r;
            int t = rg >> 6;
            int b = rg & 63;
            int off = ((b * TT + t) * DD + kc) / 2 + c2;
            ((__nv_bfloat162*)&As_hi[r][0])[c2] = xh2[off];
            ((__nv_bfloat162*)&As_lo[r][0])[c2] = xl2[off];
        }
        __syncthreads();
#pragma unroll
        for (int kk = 0; kk < 32; kk += 16) {
            wmma::fragment<wmma::matrix_b, 16, 16, 16, __nv_bfloat16, wmma::col_major> bhi, blo;
            wmma::load_matrix_sync(bhi, g_Whi[0] + (size_t)n_w * 1024 + kc + kk, 1024);
            wmma::load_matrix_sync(blo, g_Wlo[0] + (size_t)n_w * 1024 + kc + kk, 1024);
#pragma unroll
            for (int i = 0; i < 8; i++) {
                wmma::fragment<wmma::matrix_a, 16, 16, 16, __nv_bfloat16, wmma::row_major> ahi, alo;
                wmma::load_matrix_sync(ahi, &As_hi[16 * i][kk], 40);
                wmma::load_matrix_sync(alo, &As_lo[16 * i][kk], 40);
                wmma::mma_sync(acc[i], ahi, bhi, acc[i]);
                wmma::mma_sync(acc[i], ahi, blo, acc[i]);
                wmma::mma_sync(acc[i], alo, bhi, acc[i]);
            }
        }
    }
#pragma unroll
    for (int i = 0; i < 8; i++) {
        int rg = m0 + 16 * i;
        int t  = rg >> 6;
        int b0 = rg & 63;
        float* dst = g_GX0 + (size_t)(t * BB + b0) * G3 + n_w;
        wmma::store_matrix_sync(dst, acc[i], G3, wmma::mem_row_major);
    }
}

// ---------------- grid barrier ----------------
__device__ __forceinline__ void gsync(unsigned r) {
    __syncthreads();
    if (threadIdx.x == 0) {
        __threadfence();
        unsigned a = atomicAdd(&g_arrive, 1u);
        if (a == r * NBLK - 1u) {
            atomicExch(&g_release, r);
        } else {
            volatile unsigned* rel = &g_release;
            while (*rel < r) { }
        }
        __threadfence();
    }
    __syncthreads();
}

// ---------------- persistent recurrence kernel ----------------
// 96 blocks x 256 threads. block = (part, j0): part = bx/32, j0 = (bx%32)*32.
//  part 0: layer0 step t=p   : gh0 = h0(t-1)@Wh0^T, combine -> h0(t)
//  part 1: layer1 x  t=p-1   : gx1 = h0(t)@Wx1^T -> scratch
//  part 2: layer1 h  t=p-2   : gh1 = h1(t-1)@Wh1^T, combine -> h1(t)
// W_hi tile (96 x 1024 bf16) SMEM-stationary for the whole kernel.
// Per-chunk (K=32) staging of A(hi|lo packed) + W_lo via cp.async, double-buffered.
#define WHI_LD 1032              // 1024 + 8 pad
#define AS_LD 72                 // packed row: hi[0..31] | lo[32..63] | pad (144B, 16B-aligned)
#define BLO_LD 40                // 32 + 8 pad (80B rows, 16B-aligned)
#define SACC_LD 36               // 32 + 4 pad (float)
#define KCH 32                   // K per chunk
#define NCH 32                   // chunks per phase
#define SMEM_WHI_BYTES (96 * WHI_LD * 2)            // 198144
#define STAGE_BUF_ELEMS (64 * AS_LD + 96 * BLO_LD)  // 4608 + 3840 = 8448 bf16
#define STAGE_BUF_BYTES (STAGE_BUF_ELEMS * 2)       // 16896
// union region: 2 staging buffers (33792) vs sacc (3*64*36*4 = 27648) -> 33792
#define SMEM_UNION_BYTES (2 * STAGE_BUF_BYTES)
#define SMEM_TOTAL_BYTES (SMEM_WHI_BYTES + SMEM_UNION_BYTES)  // 231936

__global__ void __launch_bounds__(256) recur_kernel(
    const float* __restrict__ bx0, const float* __restrict__ bh0,
    const float* __restrict__ bx1, const float* __restrict__ bh1)
{
    extern __shared__ __align__(16) unsigned char s_raw[];
    __nv_bfloat16* Whi_s = (__nv_bfloat16*)s_raw;
    __nv_bfloat16* stage0 = (__nv_bfloat16*)(s_raw + SMEM_WHI_BYTES);
    float*         saccf  = (float*)(s_raw + SMEM_WHI_BYTES);   // union with staging

    const int tid  = threadIdx.x;
    const int wid  = tid >> 5;
    const int part = blockIdx.x >> 5;           // 0..2
    const int j0   = (blockIdx.x & 31) * 32;    // hidden slice base
    const int ms   = wid >> 1;                  // A row slice (0..3)
    const int nf   = wid & 1;                   // n sub-frag (0..1)

    const int widx = part + 1;                  // W matrix: 1=Wh0, 2=Wx1, 3=Wh1

    // ---- load this block's W_hi tile into SMEM (once per launch) ----
    {
        const uint4* src = (const uint4*)(g_Whi[widx]);
        for (int l = tid; l < 96 * 128; l += 256) {
            int r = l >> 7, c = l & 127;
            int grow = (r >> 5) * 1024 + j0 + (r & 31);
            *(uint4*)&Whi_s[r * WHI_LD + c * 8] = src[grow * 128 + c];
        }
    }
    __syncthreads();

    const uint4* wlo_src = (const uint4*)(g_Wlo[widx]);
    const float* bx = (part == 0) ? bx0 : bx1;
    const float* bh = (part == 0) ? bh0 : bh1;

    // A staging: 512 x 16B copies/chunk -> 2 per thread.
    //   l in [0,512): r = l>>3 (row 0..63), s = l&7: s<4 -> hi cols 8s..8s+7, s>=4 -> lo cols 32+8(s-4)..
    const unsigned stage_u32 = (unsigned)__cvta_generic_to_shared(stage0);

    for (int p = 0; p < 514; ++p) {
        int t;
        bool valid;
        if (part == 0)      { t = p;     valid = (t <= 511); }
        else if (part == 1) { t = p - 1; valid = (t >= 0 && t <= 511); }
        else                { t = p - 2; valid = (t >= 0 && t <= 511); }

        if (valid) {
            const __nv_bfloat16 *Ahi, *Alo;
            if (part == 0)      { Ahi = g_h0hi[(t + 1) & 1]; Alo = g_h0lo[(t + 1) & 1]; }
            else if (part == 1) { Ahi = g_h0hi[t & 1];       Alo = g_h0lo[t & 1]; }
            else                { Ahi = g_h1hi[(t + 1) & 1]; Alo = g_h1lo[(t + 1) & 1]; }

            const uint4* a_hi4 = (const uint4*)Ahi;
            const uint4* a_lo4 = (const uint4*)Alo;

            wmma::fragment<wmma::accumulator, 16, 16, 16, float> acc[3];
#pragma unroll
            for (int g = 0; g < 3; g++) wmma::fill_fragment(acc[g], 0.0f);

            // ---- staging lambda: chunk c into buffer (c&1) ----
            auto stage = [&](int c) {
                const int kq = c * (KCH / 8);                 // uint4 offset in 128-uint4 row
                const unsigned buf = stage_u32 + (unsigned)((c & 1) * STAGE_BUF_BYTES);
                // A: 512 copies -> 2 per thread (FIX: was 256, half the chunk unstaged)
#pragma unroll
                for (int i = 0; i < 2; i++) {
                    int l = tid + i * 256;
                    int r = l >> 3;          // 0..63
                    int s = l & 7;           // 0..7
                    const uint4* sp = (s < 4) ? (a_hi4 + r * 128 + kq + s)
                                              : (a_lo4 + r * 128 + kq + (s - 4));
                    int col = (s < 4) ? (s * 8) : (32 + (s - 4) * 8);
                    unsigned d = buf + (unsigned)((r * AS_LD + col) * 2);
                    CP_ASYNC16(d, (const void*)sp);
                }
                // Wlo: 384 copies (96 rows x 4 x 16B)
                {
                    int l = tid;
                    {
                        int r = l >> 2, q = l & 3;
                        int grow = (r >> 5) * 1024 + j0 + (r & 31);
                        unsigned d = buf + (unsigned)((64 * AS_LD + r * BLO_LD + q * 8) * 2);
                        CP_ASYNC16(d, (const void*)(wlo_src + grow * 128 + kq + q));
                    }
                    if (l < 128) {
                        l += 256;
                        int r = l >> 2, q = l & 3;
                        int grow = (r >> 5) * 1024 + j0 + (r & 31);
                        unsigned d = buf + (unsigned)((64 * AS_LD + r * BLO_LD + q * 8) * 2);
                        CP_ASYNC16(d, (const void*)(wlo_src + grow * 128 + kq + q));
                    }
                }
                CP_COMMIT();
            };

            stage(0);

            for (int c = 0; c < NCH; ++c) {
                CP_WAIT0();          // chunk c landed (this thread's copies)
                __syncthreads();     // visible to all; all warps done with other buffer
                if (c + 1 < NCH) stage(c + 1);   // async fill of other buffer

                const __nv_bfloat16* As  = stage0 + (c & 1) * STAGE_BUF_ELEMS;
                const __nv_bfloat16* Bls = As + 64 * AS_LD;
#pragma unroll
                for (int kk = 0; kk < KCH; kk += 16) {
                    wmma::fragment<wmma::matrix_a, 16, 16, 16, __nv_bfloat16, wmma::row_major> ahi, alo;
                    wmma::load_matrix_sync(ahi, As + ms * 16 * AS_LD + kk, AS_LD);
                    wmma::load_matrix_sync(alo, As + ms * 16 * AS_LD + 32 + kk, AS_LD);
#pragma unroll
                    for (int g = 0; g < 3; g++) {
                        wmma::fragment<wmma::matrix_b, 16, 16, 16, __nv_bfloat16, wmma::col_major> bhi, blo;
                        wmma::load_matrix_sync(bhi, &Whi_s[(g * 32 + nf * 16) * WHI_LD + c * KCH + kk], WHI_LD);
                        wmma::load_matrix_sync(blo, Bls + (g * 32 + nf * 16) * BLO_LD + kk, BLO_LD);
                        wmma::mma_sync(acc[g], ahi, bhi, acc[g]);
                        wmma::mma_sync(acc[g], ahi, blo, acc[g]);
                        wmma::mma_sync(acc[g], alo, bhi, acc[g]);
                    }
                }
            }
            __syncthreads();   // all warps done reading staging -> safe to write sacc (union)
#pragma unroll
            for (int g = 0; g < 3; g++)
                wmma::store_matrix_sync(saccf + (g * 64 + ms * 16) * SACC_LD + nf * 16,
                                        acc[g], SACC_LD, wmma::mem_row_major);
            __syncthreads();

            if (part == 1) {
                float* dst = g_gx1[t & 1];
                for (int l = tid; l < 64 * 32; l += 256) {
                    int b = l >> 5, jj = l & 31;
                    int j = j0 + jj;
                    dst[b * G3 + j]        = saccf[(0 * 64 + b) * SACC_LD + jj];
                    dst[b * G3 + 1024 + j] = saccf[(1 * 64 + b) * SACC_LD + jj];
                    dst[b * G3 + 2048 + j] = saccf[(2 * 64 + b) * SACC_LD + jj];
                }
            } else {
                __nv_bfloat16* outhi = (part == 0) ? g_h0hi[t & 1] : g_h1hi[t & 1];
                __nv_bfloat16* outlo = (part == 0) ? g_h0lo[t & 1] : g_h1lo[t & 1];
                for (int l = tid; l < 64 * 32; l += 256) {
                    int b = l >> 5, jj = l & 31;
                    int j = j0 + jj;
                    float ir, iz, in_;
                    if (part == 0) {
                        const float* gxr = g_GX0 + (size_t)(t * BB + b) * G3;
                        ir  = gxr[j]        + bx[j];
                        iz  = gxr[1024 + j] + bx[1024 + j];
                        in_ = gxr[2048 + j] + bx[2048 + j];
                    } else {
                        const float* gxr = g_gx1[t & 1] + b * G3;
                        ir  = gxr[j]        + bx[j];
                        iz  = gxr[1024 + j] + bx[1024 + j];
                        in_ = gxr[2048 + j] + bx[2048 + j];
                    }
                    float hr = saccf[(0 * 64 + b) * SACC_LD + jj] + bh[j];
                    float hz = saccf[(1 * 64 + b) * SACC_LD + jj] + bh[1024 + j];
                    float hn = saccf[(2 * 64 + b) * SACC_LD + jj] + bh[2048 + j];

                    float r = 1.0f / (1.0f + expf(-(ir + hr)));
                    float z = 1.0f / (1.0f + expf(-(iz + hz)));
                    float n = tanhf(in_ + r * hn);
                    float hp = __bfloat162float(Ahi[b * HH + j]) + __bfloat162float(Alo[b * HH + j]);
                    float hnew = n + z * (hp - n);

                    __nv_bfloat16 hh = __float2bfloat16(hnew);
                    outhi[b * HH + j] = hh;
                    outlo[b * HH + j] = __float2bfloat16(hnew - __bfloat162float(hh));
                }
            }
        }

        gsync((unsigned)(p + 1));
    }
}

// ---------------- FC: out[b] = h1(511)[b,:] . fcW + fcb ----------------
__global__ void fc_kernel(const float* __restrict__ fcW, const float* __restrict__ fcb,
                          float* __restrict__ out) {
    const int b = blockIdx.x;
    const int tid = threadIdx.x;
    const __nv_bfloat16* hh = g_h1hi[1] + b * HH;   // t=511 -> buffer 1
    const __nv_bfloat16* hl = g_h1lo[1] + b * HH;
    float s = 0.0f;
    for (int k = tid; k < HH; k += 128)
        s += (__bfloat162float(hh[k]) + __bfloat162float(hl[k])) * fcW[k];
    __shared__ float red[128];
    red[tid] = s;
    __syncthreads();
    for (int o = 64; o > 0; o >>= 1) {
        if (tid < o) red[tid] += red[tid + o];
        __syncthreads();
    }
    if (tid == 0) out[b] = red[0] + fcb[0];
}

// ---------------- host ----------------
extern "C" void kernel_launch(void* const* d_in, const int* in_sizes, int n_in,
                              void* d_out, int out_size) {
    const float* x   = (const float*)d_in[0];
    const float* Wx0 = (const float*)d_in[1];
    const float* bx0 = (const float*)d_in[2];
    const float* Wh0 = (const float*)d_in[3];
    const float* bh0 = (const float*)d_in[4];
    const float* Wx1 = (const float*)d_in[5];
    const float* bx1 = (const float*)d_in[6];
    const float* Wh1 = (const float*)d_in[7];
    const float* bh1 = (const float*)d_in[8];
    const float* fcW = (const float*)d_in[9];
    const float* fcb = (const float*)d_in[10];
    float* out = (float*)d_out;

    const int nW = G3 * HH;
    const int nX = BB * TT * DD;

    static int smem_set = 0;
    if (!smem_set) {
        cudaFuncSetAttribute(recur_kernel, cudaFuncAttributeMaxDynamicSharedMemorySize,
                             SMEM_TOTAL_BYTES);
        smem_set = 1;
    }

    // 1) split weights + x into bf16 hi/lo
    split_kernel<<<1024, 256>>>(0, Wx0, nW);
    split_kernel<<<1024, 256>>>(1, Wh0, nW);
    split_kernel<<<1024, 256>>>(2, Wx1, nW);
    split_kernel<<<1024, 256>>>(3, Wh1, nW);
    split_kernel<<<4096, 256>>>(4, x, nX);

    // 2) zero initial hidden states + reset grid barrier
    init_state_kernel<<<(2 * BB * HH + 255) / 256, 256>>>();

    // 3) parallel x-projection for layer 0
    {
        dim3 grid(G3 / 128, (TT * BB) / 128);   // (24, 256)
        phaseA_kernel<<<grid, 256>>>();
    }

    // 4) persistent pipelined recurrence: 514 phases, one kernel
    recur_kernel<<<NBLK, 256, SMEM_TOTAL_BYTES>>>(bx0, bh0, bx1, bh1);

    // 5) final FC
    fc_kernel<<<BB, 128>>>(fcW, fcb, out);

    (void)in_sizes; (void)n_in; (void)out_size;
}